// round 1
// baseline (speedup 1.0000x reference)
#include <cuda_runtime.h>
#include <cuda_bf16.h>
#include <cstdint>

// ---------------- problem constants ----------------
#define NODES 100000
#define HIDF  128
#define OUTF  64
#define KTOP  32

// ---------------- scratch (device globals; no allocation allowed) ----------
__device__ float g_h[(size_t)NODES * HIDF];      // dense activations
__device__ float g_t[(size_t)NODES * HIDF];      // GEMM output pre-maxk
__device__ float g_agg[(size_t)NODES * HIDF];    // scatter-add accumulator
__device__ float g_spval[(size_t)NODES * KTOP];  // sparse values (scaled by deg_out^-1/2)
__device__ unsigned char g_spidx[(size_t)NODES * KTOP];  // sparse column ids
__device__ int   g_degout[NODES];
__device__ int   g_degin[NODES];
__device__ float g_souti[NODES];                 // deg_out^-1/2
__device__ float g_sini[NODES];                  // deg_in^-1/2

// ---------------- packed fp32x2 FMA (2x fp32 rate on sm_103a) --------------
__device__ __forceinline__ void fma2(float& c0, float& c1, float a, float b0, float b1) {
    asm("{\n\t"
        ".reg .b64 ra, rb, rc;\n\t"
        "mov.b64 ra, {%2,%2};\n\t"
        "mov.b64 rb, {%3,%4};\n\t"
        "mov.b64 rc, {%0,%1};\n\t"
        "fma.rn.f32x2 rc, ra, rb, rc;\n\t"
        "mov.b64 {%0,%1}, rc;\n\t"
        "}"
        : "+f"(c0), "+f"(c1)
        : "f"(a), "f"(b0), "f"(b1));
}

// ---------------- utility kernels ----------------
__global__ void zero_f4_kernel(float4* __restrict__ p, int n4) {
    int i = blockIdx.x * blockDim.x + threadIdx.x;
    if (i < n4) p[i] = make_float4(0.f, 0.f, 0.f, 0.f);
}

__global__ void zero_deg_kernel(int n) {
    int i = blockIdx.x * blockDim.x + threadIdx.x;
    if (i < n) { g_degout[i] = 0; g_degin[i] = 0; }
}

__global__ void hist_kernel(const int* __restrict__ src, const int* __restrict__ dst, int E) {
    int e = blockIdx.x * blockDim.x + threadIdx.x;
    if (e < E) {
        atomicAdd(&g_degout[src[e]], 1);
        atomicAdd(&g_degin[dst[e]], 1);
    }
}

__global__ void degfin_kernel(int n) {
    int i = blockIdx.x * blockDim.x + threadIdx.x;
    if (i < n) {
        int dout = g_degout[i]; if (dout < 1) dout = 1;
        int din  = g_degin[i];  if (din  < 1) din  = 1;
        g_souti[i] = rsqrtf((float)dout);
        g_sini[i]  = rsqrtf((float)din);
    }
}

// ---------------- fp32 GEMM: C[M,BN] = A[M,128] @ W[128,BN] + bias ----------
// BM=64 rows/block, 256 threads, f32x2 inner product, W fully staged in smem.
template <int BN, bool RELU>
__global__ void __launch_bounds__(256) gemm_kernel(
    const float* __restrict__ A, const float* __restrict__ W,
    const float* __restrict__ bias, float* __restrict__ C, int M)
{
    constexpr int BM  = 64;
    constexpr int KK  = 128;
    constexpr int AST = 132;          // As row stride (pad, 16B-divisible)
    constexpr int CT  = BN / 4;       // threads along columns (4 cols each)
    constexpr int RT  = 256 / CT;     // threads along rows
    constexpr int RPT = BM / RT;      // rows per thread

    extern __shared__ float smem[];
    float* As = smem;                  // [BM][AST]
    float* Bs = smem + BM * AST;       // [KK][BN]

    const int tid  = threadIdx.x;
    const int row0 = blockIdx.x * BM;

    // stage W
    constexpr int WB4 = KK * BN / 4;
    for (int i = tid; i < WB4; i += 256)
        ((float4*)Bs)[i] = ((const float4*)W)[i];

    // stage A tile (zero-fill past M)
    constexpr int AB4 = BM * KK / 4;   // 2048 float4
    for (int i = tid; i < AB4; i += 256) {
        int r  = i >> 5;
        int c4 = i & 31;
        float4 v = make_float4(0.f, 0.f, 0.f, 0.f);
        if (row0 + r < M) v = ((const float4*)A)[(size_t)(row0 + r) * 32 + c4];
        *(float4*)&As[r * AST + c4 * 4] = v;
    }
    __syncthreads();

    const int tx = tid % CT;
    const int ty = tid / CT;

    float acc[RPT][4];
#pragma unroll
    for (int r = 0; r < RPT; r++) {
        acc[r][0] = 0.f; acc[r][1] = 0.f; acc[r][2] = 0.f; acc[r][3] = 0.f;
    }

#pragma unroll 4
    for (int k = 0; k < KK; k++) {
        float4 b = *(const float4*)&Bs[k * BN + tx * 4];
#pragma unroll
        for (int r = 0; r < RPT; r++) {
            float a = As[(ty * RPT + r) * AST + k];
            fma2(acc[r][0], acc[r][1], a, b.x, b.y);
            fma2(acc[r][2], acc[r][3], a, b.z, b.w);
        }
    }

    float4 bi = *(const float4*)&bias[tx * 4];
#pragma unroll
    for (int r = 0; r < RPT; r++) {
        int row = row0 + ty * RPT + r;
        if (row < M) {
            float4 o;
            o.x = acc[r][0] + bi.x;
            o.y = acc[r][1] + bi.y;
            o.z = acc[r][2] + bi.z;
            o.w = acc[r][3] + bi.w;
            if (RELU) {
                o.x = fmaxf(o.x, 0.f); o.y = fmaxf(o.y, 0.f);
                o.z = fmaxf(o.z, 0.f); o.w = fmaxf(o.w, 0.f);
            }
            *(float4*)&C[(size_t)row * BN + tx * 4] = o;
        }
    }
}

// ---------------- MaxK: exact top-32 of 128, emit sparse (val*souti, col) ---
// One warp per row; bitwise radix-select on float-order keys; ties broken by
// ascending index (matches lax.top_k stability).
__global__ void maxk_kernel(int M) {
    int warp = (blockIdx.x * blockDim.x + threadIdx.x) >> 5;
    int lane = threadIdx.x & 31;
    if (warp >= M) return;

    const float* rowp = g_t + (size_t)warp * HIDF;
    float v[4];
    unsigned key[4];
#pragma unroll
    for (int j = 0; j < 4; j++) {
        v[j] = rowp[lane + 32 * j];
        unsigned u = __float_as_uint(v[j]);
        key[j] = (u & 0x80000000u) ? ~u : (u | 0x80000000u);
    }

    // greedy bitwise max threshold T with count(key >= T) >= K  ==>  T = K-th key
    unsigned thr = 0u;
#pragma unroll
    for (int b = 31; b >= 0; b--) {
        unsigned cand = thr | (1u << b);
        int cnt = 0;
#pragma unroll
        for (int j = 0; j < 4; j++)
            cnt += __popc(__ballot_sync(0xffffffffu, key[j] >= cand));
        if (cnt >= KTOP) thr = cand;
    }

    int rem;
    {
        int cnt_gt = 0;
#pragma unroll
        for (int j = 0; j < 4; j++)
            cnt_gt += __popc(__ballot_sync(0xffffffffu, key[j] > thr));
        rem = KTOP - cnt_gt;
    }

    const float s = g_souti[warp];
    const unsigned lmlt = (1u << lane) - 1u;
    float* ov = g_spval + (size_t)warp * KTOP;
    unsigned char* oi = g_spidx + (size_t)warp * KTOP;

    int off = 0;
#pragma unroll
    for (int j = 0; j < 4; j++) {
        unsigned beq = __ballot_sync(0xffffffffu, key[j] == thr);
        int neq  = __popc(beq);
        int take = rem < neq ? rem : neq;
        if (take < 0) take = 0;
        rem -= take;
        bool sel = (key[j] > thr) || ((key[j] == thr) && (__popc(beq & lmlt) < take));
        unsigned bsel = __ballot_sync(0xffffffffu, sel);
        if (sel) {
            int pos = off + __popc(bsel & lmlt);
            ov[pos] = v[j] * s;
            oi[pos] = (unsigned char)(lane + 32 * j);
        }
        off += __popc(bsel);
    }
}

// ---------------- edge scatter: agg[dst, col] += spval[src, k] --------------
__global__ void scatter_kernel(const int* __restrict__ src, const int* __restrict__ dst, int E) {
    int gid  = blockIdx.x * blockDim.x + threadIdx.x;
    int e    = gid >> 5;
    int lane = gid & 31;
    if (e >= E) return;
    int s = 0, d = 0;
    if (lane == 0) { s = src[e]; d = dst[e]; }
    s = __shfl_sync(0xffffffffu, s, 0);
    d = __shfl_sync(0xffffffffu, d, 0);
    float val = g_spval[(size_t)s * KTOP + lane];
    int   c   = g_spidx[(size_t)s * KTOP + lane];
    atomicAdd(&g_agg[(size_t)d * HIDF + c], val);
}

// ---------------- finalize: h = agg * deg_in^-1/2 + bg ----------------------
__global__ void finalize_kernel(const float* __restrict__ bg, int M) {
    int i = blockIdx.x * blockDim.x + threadIdx.x;   // over M*32 float4
    if (i >= M * 32) return;
    int n  = i >> 5;
    int c4 = i & 31;
    float4 a = ((const float4*)g_agg)[i];
    float4 b = ((const float4*)bg)[c4];
    float sc = g_sini[n];
    float4 o;
    o.x = a.x * sc + b.x;
    o.y = a.y * sc + b.y;
    o.z = a.z * sc + b.z;
    o.w = a.w * sc + b.w;
    ((float4*)g_h)[i] = o;
}

// ---------------- launch -----------------------------------------------------
extern "C" void kernel_launch(void* const* d_in, const int* in_sizes, int n_in,
                              void* d_out, int out_size) {
    const float* x    = (const float*)d_in[0];
    const int*   src  = (const int*)d_in[1];
    const int*   dst  = (const int*)d_in[2];
    const float* W_in = (const float*)d_in[3];
    const float* b_in = (const float*)d_in[4];
    const float* W1   = (const float*)d_in[5];
    const float* b1   = (const float*)d_in[6];
    const float* bg1  = (const float*)d_in[7];
    const float* W2   = (const float*)d_in[8];
    const float* b2   = (const float*)d_in[9];
    const float* bg2  = (const float*)d_in[10];
    const float* Wo   = (const float*)d_in[11];
    const float* bo   = (const float*)d_in[12];
    float* out = (float*)d_out;

    const int M = in_sizes[0] / HIDF;   // 100000
    const int E = in_sizes[1];          // 1600000

    // dynamic smem sizes
    const int SMEM128 = (64 * 132 + 128 * 128) * 4;  // 99328
    const int SMEM64  = (64 * 132 + 128 * 64) * 4;   // 66560
    cudaFuncSetAttribute(gemm_kernel<128, true>,  cudaFuncAttributeMaxDynamicSharedMemorySize, SMEM128);
    cudaFuncSetAttribute(gemm_kernel<128, false>, cudaFuncAttributeMaxDynamicSharedMemorySize, SMEM128);
    cudaFuncSetAttribute(gemm_kernel<64,  false>, cudaFuncAttributeMaxDynamicSharedMemorySize, SMEM64);

    void *ph, *pt, *pagg;
    cudaGetSymbolAddress(&ph,   g_h);
    cudaGetSymbolAddress(&pt,   g_t);
    cudaGetSymbolAddress(&pagg, g_agg);
    float* h   = (float*)ph;
    float* t   = (float*)pt;
    float* agg = (float*)pagg;

    const int TB = 256;
    int gemm_grid = (M + 63) / 64;
    int warp_grid = (M * 32 + TB - 1) / TB;       // maxk
    int f4n       = M * 32;                        // #float4 in an [M,128] buffer
    int zero_grid = (f4n + TB - 1) / TB;
    int scat_grid = ((size_t)E * 32 + TB - 1) / TB;

    // degrees
    zero_deg_kernel<<<(M + TB - 1) / TB, TB>>>(M);
    hist_kernel<<<(E + TB - 1) / TB, TB>>>(src, dst, E);
    degfin_kernel<<<(M + TB - 1) / TB, TB>>>(M);

    // input projection + relu
    gemm_kernel<128, true><<<gemm_grid, TB, SMEM128>>>(x, W_in, b_in, h, M);

    // layer 1
    gemm_kernel<128, false><<<gemm_grid, TB, SMEM128>>>(h, W1, b1, t, M);
    maxk_kernel<<<warp_grid, TB>>>(M);
    zero_f4_kernel<<<zero_grid, TB>>>((float4*)agg, f4n);
    scatter_kernel<<<scat_grid, TB>>>(src, dst, E);
    finalize_kernel<<<zero_grid, TB>>>(bg1, M);

    // layer 2
    gemm_kernel<128, false><<<gemm_grid, TB, SMEM128>>>(h, W2, b2, t, M);
    maxk_kernel<<<warp_grid, TB>>>(M);
    zero_f4_kernel<<<zero_grid, TB>>>((float4*)agg, f4n);
    scatter_kernel<<<scat_grid, TB>>>(src, dst, E);
    finalize_kernel<<<zero_grid, TB>>>(bg2, M);

    // output projection
    gemm_kernel<64, false><<<gemm_grid, TB, SMEM64>>>(h, Wo, bo, out, M);
}

// round 2
// speedup vs baseline: 1.3554x; 1.3554x over previous
#include <cuda_runtime.h>
#include <cuda_bf16.h>
#include <cstdint>

// ---------------- problem constants ----------------
#define NODES 100000
#define EDGES 1600000
#define HIDF  128
#define OUTF  64
#define KTOP  32

// ---------------- scratch (device globals; no allocation allowed) ----------
__device__ float g_h[(size_t)NODES * HIDF];      // dense activations
__device__ float g_t[(size_t)NODES * HIDF];      // GEMM output pre-maxk
__device__ float g_spval[(size_t)NODES * KTOP];  // sparse values (scaled by deg_out^-1/2)
__device__ unsigned char g_spidx[(size_t)NODES * KTOP];  // sparse column ids
__device__ int   g_degout[NODES];
__device__ int   g_degin[NODES];                 // raw in-degree counts
__device__ float g_souti[NODES];                 // deg_out^-1/2 (clamped)
__device__ float g_sini[NODES];                  // deg_in^-1/2 (clamped)
__device__ int   g_rowptr[NODES];                // exclusive prefix of deg_in
__device__ int   g_cursor[NODES];                // fill cursor
__device__ int   g_eidx[EDGES];                  // CSR-by-dst: src node ids
__device__ int   g_bsum[128];                    // block sums for scan
__device__ int   g_bsumx[128];                   // exclusive-scanned block sums

// ---------------- packed fp32x2 FMA (2x fp32 rate on sm_103a) --------------
__device__ __forceinline__ void fma2(float& c0, float& c1, float a, float b0, float b1) {
    asm("{\n\t"
        ".reg .b64 ra, rb, rc;\n\t"
        "mov.b64 ra, {%2,%2};\n\t"
        "mov.b64 rb, {%3,%4};\n\t"
        "mov.b64 rc, {%0,%1};\n\t"
        "fma.rn.f32x2 rc, ra, rb, rc;\n\t"
        "mov.b64 {%0,%1}, rc;\n\t"
        "}"
        : "+f"(c0), "+f"(c1)
        : "f"(a), "f"(b0), "f"(b1));
}

// ---------------- degree + CSR build kernels ----------------
__global__ void zero_deg_kernel(int n) {
    int i = blockIdx.x * blockDim.x + threadIdx.x;
    if (i < n) { g_degout[i] = 0; g_degin[i] = 0; }
}

__global__ void hist_kernel(const int* __restrict__ src, const int* __restrict__ dst, int E) {
    int e = blockIdx.x * blockDim.x + threadIdx.x;
    if (e < E) {
        atomicAdd(&g_degout[src[e]], 1);
        atomicAdd(&g_degin[dst[e]], 1);
    }
}

__global__ void degfin_kernel(int n) {
    int i = blockIdx.x * blockDim.x + threadIdx.x;
    if (i < n) {
        int dout = g_degout[i]; if (dout < 1) dout = 1;
        int din  = g_degin[i];  if (din  < 1) din  = 1;
        g_souti[i] = rsqrtf((float)dout);
        g_sini[i]  = rsqrtf((float)din);
    }
}

// block-wise exclusive scan of g_degin into g_rowptr (within-block), block sums out
__global__ void __launch_bounds__(1024) scan_block_kernel(int n) {
    __shared__ int sh[1024];
    int tid = threadIdx.x;
    int i = blockIdx.x * 1024 + tid;
    int v = (i < n) ? g_degin[i] : 0;
    sh[tid] = v;
    __syncthreads();
#pragma unroll
    for (int off = 1; off < 1024; off <<= 1) {
        int t = (tid >= off) ? sh[tid - off] : 0;
        __syncthreads();
        sh[tid] += t;
        __syncthreads();
    }
    if (i < n) g_rowptr[i] = sh[tid] - v;   // exclusive within block
    if (tid == 1023) g_bsum[blockIdx.x] = sh[1023];
}

__global__ void scan_top_kernel(int nb) {
    if (threadIdx.x == 0 && blockIdx.x == 0) {
        int acc = 0;
        for (int i = 0; i < nb; i++) { g_bsumx[i] = acc; acc += g_bsum[i]; }
    }
}

__global__ void scan_add_kernel(int n) {
    int i = blockIdx.x * blockDim.x + threadIdx.x;
    if (i < n) {
        int r = g_rowptr[i] + g_bsumx[i >> 10];
        g_rowptr[i] = r;
        g_cursor[i] = r;
    }
}

__global__ void fill_kernel(const int* __restrict__ src, const int* __restrict__ dst, int E) {
    int e = blockIdx.x * blockDim.x + threadIdx.x;
    if (e < E) {
        int d = dst[e];
        int pos = atomicAdd(&g_cursor[d], 1);
        g_eidx[pos] = src[e];
    }
}

// ---------------- fp32 GEMM: C[M,BN] = A[M,128] @ W[128,BN] + bias ----------
// BM=64 rows/block, 256 threads. W staged in two K=64 halves (smem 66KB for
// BN=128 -> 3 blocks/SM). Inner loop unrolled by 4 with float4 LDS.
template <int BN, bool RELU>
__global__ void __launch_bounds__(256, 3) gemm_kernel(
    const float* __restrict__ A, const float* __restrict__ W,
    const float* __restrict__ bias, float* __restrict__ C, int M)
{
    constexpr int BM  = 64;
    constexpr int KK  = 128;
    constexpr int AST = 132;          // As row stride (pad, float4-divisible)
    constexpr int CT  = BN / 4;       // threads along columns (4 cols each)
    constexpr int RT  = 256 / CT;     // threads along rows
    constexpr int RPT = BM / RT;      // rows per thread

    extern __shared__ float smem[];
    float* As = smem;                  // [BM][AST]
    float* Bs = smem + BM * AST;       // [64][BN] (half of W at a time)

    const int tid  = threadIdx.x;
    const int row0 = blockIdx.x * BM;

    // stage A tile (zero-fill past M) — full K=128
    constexpr int AB4 = BM * KK / 4;   // 2048 float4
    for (int i = tid; i < AB4; i += 256) {
        int r  = i >> 5;
        int c4 = i & 31;
        float4 v = make_float4(0.f, 0.f, 0.f, 0.f);
        if (row0 + r < M) v = ((const float4*)A)[(size_t)(row0 + r) * 32 + c4];
        *(float4*)&As[r * AST + c4 * 4] = v;
    }

    const int tx = tid % CT;
    const int ty = tid / CT;

    float acc[RPT][4];
#pragma unroll
    for (int r = 0; r < RPT; r++) {
        acc[r][0] = 0.f; acc[r][1] = 0.f; acc[r][2] = 0.f; acc[r][3] = 0.f;
    }

    constexpr int WB4 = 64 * BN / 4;   // float4s per W half

#pragma unroll
    for (int ks = 0; ks < 2; ks++) {
        // stage this K-half of W
        for (int i = tid; i < WB4; i += 256)
            ((float4*)Bs)[i] = ((const float4*)W)[ks * WB4 + i];
        __syncthreads();

#pragma unroll 4
        for (int k4 = 0; k4 < 16; k4++) {
            float4 b0 = *(const float4*)&Bs[(k4 * 4 + 0) * BN + tx * 4];
            float4 b1 = *(const float4*)&Bs[(k4 * 4 + 1) * BN + tx * 4];
            float4 b2 = *(const float4*)&Bs[(k4 * 4 + 2) * BN + tx * 4];
            float4 b3 = *(const float4*)&Bs[(k4 * 4 + 3) * BN + tx * 4];
#pragma unroll
            for (int r = 0; r < RPT; r++) {
                float4 a = *(const float4*)&As[(ty * RPT + r) * AST + ks * 64 + k4 * 4];
                fma2(acc[r][0], acc[r][1], a.x, b0.x, b0.y);
                fma2(acc[r][2], acc[r][3], a.x, b0.z, b0.w);
                fma2(acc[r][0], acc[r][1], a.y, b1.x, b1.y);
                fma2(acc[r][2], acc[r][3], a.y, b1.z, b1.w);
                fma2(acc[r][0], acc[r][1], a.z, b2.x, b2.y);
                fma2(acc[r][2], acc[r][3], a.z, b2.z, b2.w);
                fma2(acc[r][0], acc[r][1], a.w, b3.x, b3.y);
                fma2(acc[r][2], acc[r][3], a.w, b3.z, b3.w);
            }
        }
        __syncthreads();
    }

    float4 bi = *(const float4*)&bias[tx * 4];
#pragma unroll
    for (int r = 0; r < RPT; r++) {
        int row = row0 + ty * RPT + r;
        if (row < M) {
            float4 o;
            o.x = acc[r][0] + bi.x;
            o.y = acc[r][1] + bi.y;
            o.z = acc[r][2] + bi.z;
            o.w = acc[r][3] + bi.w;
            if (RELU) {
                o.x = fmaxf(o.x, 0.f); o.y = fmaxf(o.y, 0.f);
                o.z = fmaxf(o.z, 0.f); o.w = fmaxf(o.w, 0.f);
            }
            *(float4*)&C[(size_t)row * BN + tx * 4] = o;
        }
    }
}

// ---------------- MaxK: exact top-32 of 128, emit sparse (val*souti, col) ---
__global__ void maxk_kernel(int M) {
    int warp = (blockIdx.x * blockDim.x + threadIdx.x) >> 5;
    int lane = threadIdx.x & 31;
    if (warp >= M) return;

    const float* rowp = g_t + (size_t)warp * HIDF;
    float v[4];
    unsigned key[4];
#pragma unroll
    for (int j = 0; j < 4; j++) {
        v[j] = rowp[lane + 32 * j];
        unsigned u = __float_as_uint(v[j]);
        key[j] = (u & 0x80000000u) ? ~u : (u | 0x80000000u);
    }

    unsigned thr = 0u;
#pragma unroll
    for (int b = 31; b >= 0; b--) {
        unsigned cand = thr | (1u << b);
        int cnt = 0;
#pragma unroll
        for (int j = 0; j < 4; j++)
            cnt += __popc(__ballot_sync(0xffffffffu, key[j] >= cand));
        if (cnt >= KTOP) thr = cand;
    }

    int rem;
    {
        int cnt_gt = 0;
#pragma unroll
        for (int j = 0; j < 4; j++)
            cnt_gt += __popc(__ballot_sync(0xffffffffu, key[j] > thr));
        rem = KTOP - cnt_gt;
    }

    const float s = g_souti[warp];
    const unsigned lmlt = (1u << lane) - 1u;
    float* ov = g_spval + (size_t)warp * KTOP;
    unsigned char* oi = g_spidx + (size_t)warp * KTOP;

    int off = 0;
#pragma unroll
    for (int j = 0; j < 4; j++) {
        unsigned beq = __ballot_sync(0xffffffffu, key[j] == thr);
        int neq  = __popc(beq);
        int take = rem < neq ? rem : neq;
        if (take < 0) take = 0;
        rem -= take;
        bool sel = (key[j] > thr) || ((key[j] == thr) && (__popc(beq & lmlt) < take));
        unsigned bsel = __ballot_sync(0xffffffffu, sel);
        if (sel) {
            int pos = off + __popc(bsel & lmlt);
            ov[pos] = v[j] * s;
            oi[pos] = (unsigned char)(lane + 32 * j);
        }
        off += __popc(bsel);
    }
}

// ---------------- CSR gather: h[d,:] = sini[d] * sum_{e in in(d)} sp[src_e] + bg
// One warp per dst node; private 128-float smem row; non-atomic RMW (cols are
// distinct within one edge; __syncwarp orders across edges).
__global__ void __launch_bounds__(256) gather_kernel(const float* __restrict__ bg, int M) {
    __shared__ float rowbuf[8][128];
    int w    = (blockIdx.x * blockDim.x + threadIdx.x) >> 5;
    int lane = threadIdx.x & 31;
    int wl   = threadIdx.x >> 5;
    if (w >= M) return;

    float* rb = rowbuf[wl];
    rb[lane] = 0.f; rb[lane + 32] = 0.f; rb[lane + 64] = 0.f; rb[lane + 96] = 0.f;

    const int beg = g_rowptr[w];
    const int deg = g_degin[w];
    const int end = beg + deg;

    for (int base = beg; base < end; base += 32) {
        int cnt = end - base; if (cnt > 32) cnt = 32;
        int s_l = (lane < cnt) ? g_eidx[base + lane] : 0;

        int   s0 = __shfl_sync(0xffffffffu, s_l, 0);
        float v  = g_spval[(size_t)s0 * KTOP + lane];
        int   c  = g_spidx[(size_t)s0 * KTOP + lane];

        for (int j = 0; j < cnt; j++) {
            float vc = v; int cc = c;
            if (j + 1 < cnt) {
                int sn = __shfl_sync(0xffffffffu, s_l, j + 1);
                v = g_spval[(size_t)sn * KTOP + lane];
                c = g_spidx[(size_t)sn * KTOP + lane];
            }
            rb[cc] += vc;
            __syncwarp();
        }
    }

    const float sc = g_sini[w];
    float4 a = *(float4*)&rb[lane * 4];
    float4 b = ((const float4*)bg)[lane];
    float4 o;
    o.x = a.x * sc + b.x;
    o.y = a.y * sc + b.y;
    o.z = a.z * sc + b.z;
    o.w = a.w * sc + b.w;
    ((float4*)(g_h + (size_t)w * HIDF))[lane] = o;
}

// ---------------- launch -----------------------------------------------------
extern "C" void kernel_launch(void* const* d_in, const int* in_sizes, int n_in,
                              void* d_out, int out_size) {
    const float* x    = (const float*)d_in[0];
    const int*   src  = (const int*)d_in[1];
    const int*   dst  = (const int*)d_in[2];
    const float* W_in = (const float*)d_in[3];
    const float* b_in = (const float*)d_in[4];
    const float* W1   = (const float*)d_in[5];
    const float* b1   = (const float*)d_in[6];
    const float* bg1  = (const float*)d_in[7];
    const float* W2   = (const float*)d_in[8];
    const float* b2   = (const float*)d_in[9];
    const float* bg2  = (const float*)d_in[10];
    const float* Wo   = (const float*)d_in[11];
    const float* bo   = (const float*)d_in[12];
    float* out = (float*)d_out;

    const int M = in_sizes[0] / HIDF;   // 100000
    const int E = in_sizes[1];          // 1600000

    const int SMEM128 = (64 * 132 + 64 * 128) * 4;  // 66560
    const int SMEM64  = (64 * 132 + 64 * 64) * 4;   // 50176
    cudaFuncSetAttribute(gemm_kernel<128, true>,  cudaFuncAttributeMaxDynamicSharedMemorySize, SMEM128);
    cudaFuncSetAttribute(gemm_kernel<128, false>, cudaFuncAttributeMaxDynamicSharedMemorySize, SMEM128);
    cudaFuncSetAttribute(gemm_kernel<64,  false>, cudaFuncAttributeMaxDynamicSharedMemorySize, SMEM64);

    void *ph, *pt;
    cudaGetSymbolAddress(&ph, g_h);
    cudaGetSymbolAddress(&pt, g_t);
    float* h = (float*)ph;
    float* t = (float*)pt;

    const int TB = 256;
    const int gemm_grid = (M + 63) / 64;
    const int warp_grid = (M * 32 + TB - 1) / TB;      // 1 warp per node
    const int node_grid = (M + TB - 1) / TB;
    const int edge_grid = (E + TB - 1) / TB;
    const int NB        = (M + 1023) / 1024;           // scan blocks

    // ---- degrees + CSR build (once per launch) ----
    zero_deg_kernel<<<node_grid, TB>>>(M);
    hist_kernel<<<edge_grid, TB>>>(src, dst, E);
    degfin_kernel<<<node_grid, TB>>>(M);
    scan_block_kernel<<<NB, 1024>>>(M);
    scan_top_kernel<<<1, 32>>>(NB);
    scan_add_kernel<<<node_grid, TB>>>(M);
    fill_kernel<<<edge_grid, TB>>>(src, dst, E);

    // ---- input projection + relu ----
    gemm_kernel<128, true><<<gemm_grid, TB, SMEM128>>>(x, W_in, b_in, h, M);

    // ---- layer 1 ----
    gemm_kernel<128, false><<<gemm_grid, TB, SMEM128>>>(h, W1, b1, t, M);
    maxk_kernel<<<warp_grid, TB>>>(M);
    gather_kernel<<<warp_grid, TB>>>(bg1, M);

    // ---- layer 2 ----
    gemm_kernel<128, false><<<gemm_grid, TB, SMEM128>>>(h, W2, b2, t, M);
    maxk_kernel<<<warp_grid, TB>>>(M);
    gather_kernel<<<warp_grid, TB>>>(bg2, M);

    // ---- output projection ----
    gemm_kernel<64, false><<<gemm_grid, TB, SMEM64>>>(h, Wo, bo, out, M);
}